// round 10
// baseline (speedup 1.0000x reference)
#include <cuda_runtime.h>

#define Bn 4
#define Cn 3
#define HW 1024
#define NT 32            // 32x32 tiles per image dim
#define OP 31            // output positions per dim
#define PP (OP*OP)       // 961
#define NPOS (Bn*PP)     // 3844
#define NPOSP 4096       // padded to 16*256
#define MBLK 16          // mlp blocks (16*256 >= NPOS)
#define TSGRID 768       // tilesum blocks: one wave at 6 CTAs/SM, 4 chunks each
#define APGRID (MBLK + Bn*Cn*64)   // 16 mlp + 768 apply blocks
#define INVW (1.0f/4096.0f)
#define INVP (1.0f/3844.0f)
#define EPSV 1e-5f
#define SCL  (30.0f/1023.0f)

// ---- scratch (device globals; no allocation allowed) ----
__device__ unsigned g_c2;      // 16-block barrier counter (self-resets)
__device__ unsigned g_p2;      // 16-block barrier phase (monotonic, replay-safe)
__device__ unsigned g_mdone;   // mlp completion count (reset by k_tilesum)
__device__ unsigned g_flag;    // one-way release flag   (reset by k_tilesum)
__device__ float g_tile[4][Bn][Cn][NT][NT];   // [stat][b][c][ty][tx]
__device__ float g_part1[MBLK][64];
__device__ float g_part2[MBLK][64];
__device__ float g_A[Cn][NPOSP];
__device__ float g_Bv[Cn][NPOSP];

// ============================================================
// Kernel 1: centered 32x32 tile sums, single balanced wave.
// Also resets g_mdone/g_flag for kernel 2 (stream-ordered).
// ============================================================
__global__ __launch_bounds__(256, 6) void k_tilesum(
    const float* __restrict__ guide, const float* __restrict__ src)
{
    __shared__ float sh[8][4][4];   // [warp][tile][stat]
    const int t = threadIdx.x;
    const int w = t >> 5, l = t & 31;
    if (blockIdx.x == 0 && t == 0) { g_mdone = 0u; g_flag = 0u; }

    #pragma unroll 1
    for (int i = 0; i < 4; i++) {
        int chunk = blockIdx.x * 4 + i;
        int tx4 = chunk & 7, ty = (chunk >> 3) & 31, bc = chunk >> 8;
        int col = tx4 * 128 + l * 4;
        long base0 = (((long)bc * HW) + (long)(ty * NT + w)) * HW + col;

        float4 G[4], S[4];
        #pragma unroll
        for (int rr = 0; rr < 4; rr++)
            G[rr] = *(const float4*)(guide + base0 + (long)rr * 8 * HW);
        #pragma unroll
        for (int rr = 0; rr < 4; rr++)
            S[rr] = *(const float4*)(src + base0 + (long)rr * 8 * HW);

        float s1 = 0.f, s2 = 0.f, s3 = 0.f, s4 = 0.f;
        #pragma unroll
        for (int rr = 0; rr < 4; rr++) {
            float x0 = G[rr].x - 0.5f, x1 = G[rr].y - 0.5f,
                  x2 = G[rr].z - 0.5f, x3 = G[rr].w - 0.5f;
            float y0 = S[rr].x - 0.5f, y1 = S[rr].y - 0.5f,
                  y2 = S[rr].z - 0.5f, y3 = S[rr].w - 0.5f;
            s1 += x0 + x1 + x2 + x3;
            s2 += y0 + y1 + y2 + y3;
            s3 = fmaf(x0, y0, fmaf(x1, y1, fmaf(x2, y2, fmaf(x3, y3, s3))));
            s4 = fmaf(x0, x0, fmaf(x1, x1, fmaf(x2, x2, fmaf(x3, x3, s4))));
        }
        #pragma unroll
        for (int o = 4; o; o >>= 1) {
            s1 += __shfl_down_sync(0xffffffffu, s1, o, 8);
            s2 += __shfl_down_sync(0xffffffffu, s2, o, 8);
            s3 += __shfl_down_sync(0xffffffffu, s3, o, 8);
            s4 += __shfl_down_sync(0xffffffffu, s4, o, 8);
        }
        if ((l & 7) == 0) {
            int tt = l >> 3;
            sh[w][tt][0]=s1; sh[w][tt][1]=s2; sh[w][tt][2]=s3; sh[w][tt][3]=s4;
        }
        __syncthreads();
        if (t < 16) {
            int tt = t >> 2, st = t & 3;
            float s = 0.f;
            #pragma unroll
            for (int q = 0; q < 8; q++) s += sh[q][tt][st];
            int b = bc / Cn, c = bc - b * Cn;
            g_tile[st][b][c][ty][tx4 * 4 + tt] = s;
        }
        __syncthreads();
    }
}

// ------------------------------------------------------------
// Sense-reversing barrier among the 16 co-resident mlp blocks.
// ------------------------------------------------------------
__device__ __forceinline__ void bar16()
{
    __syncthreads();
    if (threadIdx.x == 0) {
        __threadfence();
        unsigned ph = *(volatile unsigned*)&g_p2;
        if (atomicAdd(&g_c2, 1u) + 1u == MBLK) {
            g_c2 = 0u;
            __threadfence();
            atomicAdd(&g_p2, 1u);
        } else {
            while (*(volatile unsigned*)&g_p2 == ph) __nanosleep(32);
        }
        __threadfence();
    }
    __syncthreads();
}

// ============================================================
// Kernel 2: blocks 0..15 run the MLP then raise a one-way flag;
// blocks 16..783 wait once on the flag, then upsample + apply.
// No deadlock possible: flag is one-way, waiters need nothing
// from each other, and the 16 mlp blocks are wave-1 resident.
// ============================================================
__global__ void k_mlp_apply(
    const float* __restrict__ guide,
    const float* __restrict__ w1, const float* __restrict__ gg1,
    const float* __restrict__ bb1, const float* __restrict__ w2,
    const float* __restrict__ gg2, const float* __restrict__ bb2,
    const float* __restrict__ w3, float* __restrict__ out)
{
    const int t = threadIdx.x;
    const int blk = blockIdx.x;

    if (blk < MBLK) {
        // ================= MLP path =================
        __shared__ float sw1[192], sw2[1024], sw3[96], sbn[128];
        __shared__ float sred[8][64], ssum[64], ssc[32], ssf[32];
        const int w = t >> 5, l = t & 31;
        const int pos = blk * 256 + t;
        const bool act = pos < NPOS;

        for (int idx = t; idx < 192; idx += 256) sw1[idx] = w1[idx];
        for (int idx = t; idx < 1024; idx += 256) sw2[idx] = w2[idx];
        if (t < 96) sw3[t] = w3[t];
        if (t < 32) { sbn[t]=gg1[t]; sbn[32+t]=bb1[t]; sbn[64+t]=gg2[t]; sbn[96+t]=bb2[t]; }
        __syncthreads();

        // ---- window stats ----
        int cpos = act ? pos : 0;
        int b = cpos / PP; int p = cpos - b * PP; int i = p / OP; int j = p - i * OP;

        float h[6], mx[3], my[3];
        #pragma unroll
        for (int c = 0; c < Cn; c++) {
            float S1 = g_tile[0][b][c][i][j] + g_tile[0][b][c][i][j+1]
                     + g_tile[0][b][c][i+1][j] + g_tile[0][b][c][i+1][j+1];
            float S2 = g_tile[1][b][c][i][j] + g_tile[1][b][c][i][j+1]
                     + g_tile[1][b][c][i+1][j] + g_tile[1][b][c][i+1][j+1];
            float S3 = g_tile[2][b][c][i][j] + g_tile[2][b][c][i][j+1]
                     + g_tile[2][b][c][i+1][j] + g_tile[2][b][c][i+1][j+1];
            float S4 = g_tile[3][b][c][i][j] + g_tile[3][b][c][i][j+1]
                     + g_tile[3][b][c][i+1][j] + g_tile[3][b][c][i+1][j+1];
            float ex = S1 * INVW, ey = S2 * INVW;
            mx[c] = ex + 0.5f;
            my[c] = ey + 0.5f;
            h[c]     = S3 * INVW - ex * ey;
            h[3 + c] = S4 * INVW - ex * ex;
        }

        // ---- layer 1 (6->32) + BN1 partials ----
        float z1[32];
        #pragma unroll
        for (int k = 0; k < 32; k++) {
            float z = 0.f;
            #pragma unroll
            for (int cc = 0; cc < 6; cc++) z = fmaf(sw1[k*6 + cc], h[cc], z);
            z1[k] = z;
            float v  = act ? z : 0.f;
            float v2 = v * v;
            #pragma unroll
            for (int o = 16; o; o >>= 1) {
                v  += __shfl_down_sync(0xffffffffu, v,  o);
                v2 += __shfl_down_sync(0xffffffffu, v2, o);
            }
            if (l == 0) { sred[w][k] = v; sred[w][32 + k] = v2; }
        }
        __syncthreads();
        if (t < 64) {
            float s = 0.f;
            #pragma unroll
            for (int q = 0; q < 8; q++) s += sred[q][t];
            g_part1[blk][t] = s;
        }

        bar16();      // BN1 reduction point

        if (t < 64) {
            float s = 0.f;
            #pragma unroll
            for (int ib = 0; ib < MBLK; ib++) s += g_part1[ib][t];
            ssum[t] = s;
        }
        __syncthreads();
        if (t < 32) {
            float m   = ssum[t] * INVP;
            float var = ssum[32 + t] * INVP - m * m;
            float sc  = sbn[t] * rsqrtf(var + EPSV);
            ssc[t] = sc; ssf[t] = sbn[32 + t] - m * sc;
        }
        __syncthreads();
        #pragma unroll
        for (int k = 0; k < 32; k++)
            z1[k] = fmaxf(fmaf(z1[k], ssc[k], ssf[k]), 0.f);
        __syncthreads();

        // ---- layer 2 (32->32) + BN2 partials ----
        float z2[32];
        #pragma unroll
        for (int k = 0; k < 32; k++) {
            float z = 0.f;
            #pragma unroll
            for (int cc = 0; cc < 32; cc++) z = fmaf(sw2[k*32 + cc], z1[cc], z);
            z2[k] = z;
            float v  = act ? z : 0.f;
            float v2 = v * v;
            #pragma unroll
            for (int o = 16; o; o >>= 1) {
                v  += __shfl_down_sync(0xffffffffu, v,  o);
                v2 += __shfl_down_sync(0xffffffffu, v2, o);
            }
            if (l == 0) { sred[w][k] = v; sred[w][32 + k] = v2; }
        }
        __syncthreads();
        if (t < 64) {
            float s = 0.f;
            #pragma unroll
            for (int q = 0; q < 8; q++) s += sred[q][t];
            g_part2[blk][t] = s;
        }

        bar16();      // BN2 reduction point

        if (t < 64) {
            float s = 0.f;
            #pragma unroll
            for (int ib = 0; ib < MBLK; ib++) s += g_part2[ib][t];
            ssum[t] = s;
        }
        __syncthreads();
        if (t < 32) {
            float m   = ssum[t] * INVP;
            float var = ssum[32 + t] * INVP - m * m;
            float sc  = sbn[64 + t] * rsqrtf(var + EPSV);
            ssc[t] = sc; ssf[t] = sbn[96 + t] - m * sc;
        }
        __syncthreads();
        #pragma unroll
        for (int k = 0; k < 32; k++)
            z2[k] = fmaxf(fmaf(z2[k], ssc[k], ssf[k]), 0.f);

        // ---- layer 3 (32->3) => A, b ----
        #pragma unroll
        for (int c = 0; c < Cn; c++) {
            float A = 0.f;
            #pragma unroll
            for (int k = 0; k < 32; k++) A = fmaf(sw3[c*32 + k], z2[k], A);
            g_A[c][pos]  = A;
            g_Bv[c][pos] = my[c] - A * mx[c];
        }

        // ---- release: last finished mlp block raises the flag ----
        __syncthreads();
        if (t == 0) {
            __threadfence();
            if (atomicAdd(&g_mdone, 1u) + 1u == MBLK)
                atomicExch(&g_flag, 1u);
        }
        return;
    }

    // ================= Apply path =================
    __shared__ float s3A[3][OP], s3B[3][OP];
    __shared__ float rA[16][32], rB[16][32];
    int a = blk - MBLK;                     // 0..767
    int bc = a >> 6;                        // plane b*3+c
    int ybase = (a & 63) * 16;
    int b = bc / Cn, c = bc - b * Cn;
    int row0 = (int)((float)ybase * SCL);   // first coarse row needed

    int x0a[4]; float wxa[4];
    #pragma unroll
    for (int u = 0; u < 4; u++) {
        float fx = (float)(t * 4 + u) * SCL;
        x0a[u] = (int)fx;
        wxa[u] = fx - (float)x0a[u];
    }

    // one-way wait for A,b (read-only spin; no RMW contention)
    if (t == 0) {
        while (*(volatile unsigned*)&g_flag == 0u) __nanosleep(128);
        __threadfence();   // acquire
    }
    __syncthreads();

    if (t < 93) {
        int k = t / OP, j = t - k * OP;
        int rsrc = min(row0 + k, OP - 1);
        s3A[k][j] = g_A[c][b * PP + rsrc * OP + j];
        s3B[k][j] = g_Bv[c][b * PP + rsrc * OP + j];
    }
    __syncthreads();

    for (int e = t; e < 512; e += 256) {
        int ry = e >> 5, col = e & 31;
        float fy = (float)(ybase + ry) * SCL;
        int y0 = (int)fy;
        float wy = fy - (float)y0;
        int y0l = y0 - row0;
        int y1l = min(y0 + 1, OP - 1) - row0;
        int xi = min(col, OP - 1);          // col 31 duplicates col 30 (clamp)
        rA[ry][col] = s3A[y0l][xi] * (1.f - wy) + s3A[y1l][xi] * wy;
        rB[ry][col] = s3B[y0l][xi] * (1.f - wy) + s3B[y1l][xi] * wy;
    }
    __syncthreads();

    long pbase = ((long)bc * HW + ybase) * (long)HW;
    const float4* gp = (const float4*)(guide + pbase);
    float4* op = (float4*)(out + pbase);

    #pragma unroll 4
    for (int ry = 0; ry < 16; ry++) {
        float4 g = gp[ry * 256 + t];
        float av[4], bv[4];
        #pragma unroll
        for (int u = 0; u < 4; u++) {
            av[u] = rA[ry][x0a[u]] * (1.f - wxa[u]) + rA[ry][x0a[u] + 1] * wxa[u];
            bv[u] = rB[ry][x0a[u]] * (1.f - wxa[u]) + rB[ry][x0a[u] + 1] * wxa[u];
        }
        float4 r;
        r.x = fmaf(av[0], g.x, bv[0]);
        r.y = fmaf(av[1], g.y, bv[1]);
        r.z = fmaf(av[2], g.z, bv[2]);
        r.w = fmaf(av[3], g.w, bv[3]);
        op[ry * 256 + t] = r;
    }
}

// ============================================================
extern "C" void kernel_launch(void* const* d_in, const int* in_sizes, int n_in,
                              void* d_out, int out_size)
{
    const float* guide = (const float*)d_in[0];
    const float* src   = (const float*)d_in[1];
    // d_in[2] = box_w (all ones) — window count is constant 4096, unused
    const float* w1 = (const float*)d_in[3];
    const float* g1 = (const float*)d_in[4];
    const float* b1 = (const float*)d_in[5];
    const float* w2 = (const float*)d_in[6];
    const float* g2 = (const float*)d_in[7];
    const float* b2 = (const float*)d_in[8];
    const float* w3 = (const float*)d_in[9];
    float* out = (float*)d_out;

    k_tilesum<<<TSGRID, 256>>>(guide, src);
    k_mlp_apply<<<APGRID, 256>>>(guide, w1, g1, b1, w2, g2, b2, w3, out);
}

// round 11
// speedup vs baseline: 1.0418x; 1.0418x over previous
#include <cuda_runtime.h>

#define Bn 4
#define Cn 3
#define HW 1024
#define NT 32            // 32x32 tiles per image dim
#define OP 31            // output positions per dim
#define PP (OP*OP)       // 961
#define NPOS (Bn*PP)     // 3844
#define NPOSP 4096       // padded to 16*256
#define MBLK 16          // mlp blocks (16*256 >= NPOS)
#define TSGRID 768       // tilesum blocks: one wave at 6 CTAs/SM, 4 chunks each
#define INVW (1.0f/4096.0f)
#define INVP (1.0f/3844.0f)
#define EPSV 1e-5f
#define SCL  (30.0f/1023.0f)

// ---- scratch (device globals; no allocation allowed) ----
__device__ unsigned g_c2;      // 16-block barrier counter (self-resets)
__device__ unsigned g_p2;      // 16-block barrier phase (monotonic, replay-safe)
__device__ float g_tile[4][Bn][Cn][NT][NT];   // [stat][b][c][ty][tx]
__device__ float g_part1[MBLK][64];
__device__ float g_part2[MBLK][64];
__device__ float g_A[Cn][NPOSP];
__device__ float g_Bv[Cn][NPOSP];

// ============================================================
// Kernel 1: centered 32x32 tile sums, single balanced wave.
// Triggers dependent launch right after its last global store.
// ============================================================
__global__ __launch_bounds__(256, 6) void k_tilesum(
    const float* __restrict__ guide, const float* __restrict__ src)
{
    __shared__ float sh[8][4][4];   // [warp][tile][stat]
    const int t = threadIdx.x;
    const int w = t >> 5, l = t & 31;

    #pragma unroll 1
    for (int i = 0; i < 4; i++) {
        int chunk = blockIdx.x * 4 + i;
        int tx4 = chunk & 7, ty = (chunk >> 3) & 31, bc = chunk >> 8;
        int col = tx4 * 128 + l * 4;
        long base0 = (((long)bc * HW) + (long)(ty * NT + w)) * HW + col;

        float4 G[4], S[4];
        #pragma unroll
        for (int rr = 0; rr < 4; rr++)
            G[rr] = *(const float4*)(guide + base0 + (long)rr * 8 * HW);
        #pragma unroll
        for (int rr = 0; rr < 4; rr++)
            S[rr] = *(const float4*)(src + base0 + (long)rr * 8 * HW);

        float s1 = 0.f, s2 = 0.f, s3 = 0.f, s4 = 0.f;
        #pragma unroll
        for (int rr = 0; rr < 4; rr++) {
            float x0 = G[rr].x - 0.5f, x1 = G[rr].y - 0.5f,
                  x2 = G[rr].z - 0.5f, x3 = G[rr].w - 0.5f;
            float y0 = S[rr].x - 0.5f, y1 = S[rr].y - 0.5f,
                  y2 = S[rr].z - 0.5f, y3 = S[rr].w - 0.5f;
            s1 += x0 + x1 + x2 + x3;
            s2 += y0 + y1 + y2 + y3;
            s3 = fmaf(x0, y0, fmaf(x1, y1, fmaf(x2, y2, fmaf(x3, y3, s3))));
            s4 = fmaf(x0, x0, fmaf(x1, x1, fmaf(x2, x2, fmaf(x3, x3, s4))));
        }
        #pragma unroll
        for (int o = 4; o; o >>= 1) {
            s1 += __shfl_down_sync(0xffffffffu, s1, o, 8);
            s2 += __shfl_down_sync(0xffffffffu, s2, o, 8);
            s3 += __shfl_down_sync(0xffffffffu, s3, o, 8);
            s4 += __shfl_down_sync(0xffffffffu, s4, o, 8);
        }
        if ((l & 7) == 0) {
            int tt = l >> 3;
            sh[w][tt][0]=s1; sh[w][tt][1]=s2; sh[w][tt][2]=s3; sh[w][tt][3]=s4;
        }
        __syncthreads();
        if (t < 16) {
            int tt = t >> 2, st = t & 3;
            float s = 0.f;
            #pragma unroll
            for (int q = 0; q < 8; q++) s += sh[q][tt][st];
            int b = bc / Cn, c = bc - b * Cn;
            g_tile[st][b][c][ty][tx4 * 4 + tt] = s;
        }
        __syncthreads();
    }
    cudaTriggerProgrammaticLaunchCompletion();
}

// ------------------------------------------------------------
// Sense-reversing barrier among the 16 co-resident mlp blocks.
// Counter self-resets before release => reusable & replay-safe.
// ------------------------------------------------------------
__device__ __forceinline__ void bar16()
{
    __syncthreads();
    if (threadIdx.x == 0) {
        __threadfence();
        unsigned ph = *(volatile unsigned*)&g_p2;
        if (atomicAdd(&g_c2, 1u) + 1u == MBLK) {
            g_c2 = 0u;
            __threadfence();
            atomicAdd(&g_p2, 1u);
        } else {
            while (*(volatile unsigned*)&g_p2 == ph) __nanosleep(32);
        }
        __threadfence();
    }
    __syncthreads();
}

// ============================================================
// Kernel 2: fused MLP. PDL-dependent on k_tilesum: blocks start
// early, stage weights into smem, THEN grid-dep-sync before
// touching g_tile.
// ============================================================
__global__ void k_mlp(
    const float* __restrict__ w1, const float* __restrict__ gg1,
    const float* __restrict__ bb1, const float* __restrict__ w2,
    const float* __restrict__ gg2, const float* __restrict__ bb2,
    const float* __restrict__ w3)
{
    __shared__ float sw1[192], sw2[1024], sw3[96], sbn[128];
    __shared__ float sred[8][64], ssum[64], ssc[32], ssf[32];

    const int t = threadIdx.x;
    const int w = t >> 5, l = t & 31;
    const int blk = blockIdx.x;
    const int pos = blk * 256 + t;
    const bool act = pos < NPOS;

    // stage weights while predecessor may still be running
    for (int idx = t; idx < 192; idx += 256) sw1[idx] = w1[idx];
    for (int idx = t; idx < 1024; idx += 256) sw2[idx] = w2[idx];
    if (t < 96) sw3[t] = w3[t];
    if (t < 32) { sbn[t]=gg1[t]; sbn[32+t]=bb1[t]; sbn[64+t]=gg2[t]; sbn[96+t]=bb2[t]; }

    cudaGridDependencySynchronize();    // wait for g_tile
    __syncthreads();

    // ---- window stats ----
    int cpos = act ? pos : 0;
    int b = cpos / PP; int p = cpos - b * PP; int i = p / OP; int j = p - i * OP;

    float h[6], mx[3], my[3];
    #pragma unroll
    for (int c = 0; c < Cn; c++) {
        float S1 = g_tile[0][b][c][i][j] + g_tile[0][b][c][i][j+1]
                 + g_tile[0][b][c][i+1][j] + g_tile[0][b][c][i+1][j+1];
        float S2 = g_tile[1][b][c][i][j] + g_tile[1][b][c][i][j+1]
                 + g_tile[1][b][c][i+1][j] + g_tile[1][b][c][i+1][j+1];
        float S3 = g_tile[2][b][c][i][j] + g_tile[2][b][c][i][j+1]
                 + g_tile[2][b][c][i+1][j] + g_tile[2][b][c][i+1][j+1];
        float S4 = g_tile[3][b][c][i][j] + g_tile[3][b][c][i][j+1]
                 + g_tile[3][b][c][i+1][j] + g_tile[3][b][c][i+1][j+1];
        float ex = S1 * INVW, ey = S2 * INVW;
        mx[c] = ex + 0.5f;
        my[c] = ey + 0.5f;
        h[c]     = S3 * INVW - ex * ey;   // cov_xy (centered)
        h[3 + c] = S4 * INVW - ex * ex;   // var_x
    }

    // ---- layer 1 (6->32) + BN1 partials ----
    float z1[32];
    #pragma unroll
    for (int k = 0; k < 32; k++) {
        float z = 0.f;
        #pragma unroll
        for (int cc = 0; cc < 6; cc++) z = fmaf(sw1[k*6 + cc], h[cc], z);
        z1[k] = z;
        float v  = act ? z : 0.f;
        float v2 = v * v;
        #pragma unroll
        for (int o = 16; o; o >>= 1) {
            v  += __shfl_down_sync(0xffffffffu, v,  o);
            v2 += __shfl_down_sync(0xffffffffu, v2, o);
        }
        if (l == 0) { sred[w][k] = v; sred[w][32 + k] = v2; }
    }
    __syncthreads();
    if (t < 64) {
        float s = 0.f;
        #pragma unroll
        for (int q = 0; q < 8; q++) s += sred[q][t];
        g_part1[blk][t] = s;
    }

    bar16();      // BN1 reduction point

    if (t < 64) {
        float s = 0.f;
        #pragma unroll
        for (int ib = 0; ib < MBLK; ib++) s += g_part1[ib][t];
        ssum[t] = s;
    }
    __syncthreads();
    if (t < 32) {
        float m   = ssum[t] * INVP;
        float var = ssum[32 + t] * INVP - m * m;
        float sc  = sbn[t] * rsqrtf(var + EPSV);
        ssc[t] = sc; ssf[t] = sbn[32 + t] - m * sc;
    }
    __syncthreads();
    #pragma unroll
    for (int k = 0; k < 32; k++)
        z1[k] = fmaxf(fmaf(z1[k], ssc[k], ssf[k]), 0.f);   // a1
    __syncthreads();

    // ---- layer 2 (32->32) + BN2 partials ----
    float z2[32];
    #pragma unroll
    for (int k = 0; k < 32; k++) {
        float z = 0.f;
        #pragma unroll
        for (int cc = 0; cc < 32; cc++) z = fmaf(sw2[k*32 + cc], z1[cc], z);
        z2[k] = z;
        float v  = act ? z : 0.f;
        float v2 = v * v;
        #pragma unroll
        for (int o = 16; o; o >>= 1) {
            v  += __shfl_down_sync(0xffffffffu, v,  o);
            v2 += __shfl_down_sync(0xffffffffu, v2, o);
        }
        if (l == 0) { sred[w][k] = v; sred[w][32 + k] = v2; }
    }
    __syncthreads();
    if (t < 64) {
        float s = 0.f;
        #pragma unroll
        for (int q = 0; q < 8; q++) s += sred[q][t];
        g_part2[blk][t] = s;
    }

    bar16();      // BN2 reduction point

    if (t < 64) {
        float s = 0.f;
        #pragma unroll
        for (int ib = 0; ib < MBLK; ib++) s += g_part2[ib][t];
        ssum[t] = s;
    }
    __syncthreads();
    if (t < 32) {
        float m   = ssum[t] * INVP;
        float var = ssum[32 + t] * INVP - m * m;
        float sc  = sbn[64 + t] * rsqrtf(var + EPSV);
        ssc[t] = sc; ssf[t] = sbn[96 + t] - m * sc;
    }
    __syncthreads();
    #pragma unroll
    for (int k = 0; k < 32; k++)
        z2[k] = fmaxf(fmaf(z2[k], ssc[k], ssf[k]), 0.f);   // a2

    // ---- layer 3 (32->3) => A, b ----
    #pragma unroll
    for (int c = 0; c < Cn; c++) {
        float A = 0.f;
        #pragma unroll
        for (int k = 0; k < 32; k++) A = fmaf(sw3[c*32 + k], z2[k], A);
        g_A[c][pos]  = A;
        g_Bv[c][pos] = my[c] - A * mx[c];
    }
    cudaTriggerProgrammaticLaunchCompletion();
}

// ============================================================
// Kernel 3: bilinear upsample + apply. PDL-dependent on k_mlp:
// blocks start early, compute x-weights, THEN grid-dep-sync
// before touching g_A/g_Bv.
// ============================================================
__global__ __launch_bounds__(256) void k_apply(
    const float* __restrict__ guide, float* __restrict__ out)
{
    __shared__ float s3A[3][OP], s3B[3][OP];
    __shared__ float rA[16][32], rB[16][32];
    int t = threadIdx.x;
    int bc = blockIdx.x;
    int b = bc / Cn, c = bc - b * Cn;
    int ybase = blockIdx.y * 16;
    int row0 = (int)((float)ybase * SCL);   // first coarse row needed

    int x0a[4]; float wxa[4];
    #pragma unroll
    for (int u = 0; u < 4; u++) {
        float fx = (float)(t * 4 + u) * SCL;
        x0a[u] = (int)fx;
        wxa[u] = fx - (float)x0a[u];
    }

    cudaGridDependencySynchronize();    // wait for g_A / g_Bv

    if (t < 93) {
        int k = t / OP, j = t - k * OP;
        int rsrc = min(row0 + k, OP - 1);
        s3A[k][j] = g_A[c][b * PP + rsrc * OP + j];
        s3B[k][j] = g_Bv[c][b * PP + rsrc * OP + j];
    }
    __syncthreads();

    for (int e = t; e < 512; e += 256) {
        int ry = e >> 5, col = e & 31;
        float fy = (float)(ybase + ry) * SCL;
        int y0 = (int)fy;
        float wy = fy - (float)y0;
        int y0l = y0 - row0;
        int y1l = min(y0 + 1, OP - 1) - row0;
        int xi = min(col, OP - 1);          // col 31 duplicates col 30 (clamp)
        rA[ry][col] = s3A[y0l][xi] * (1.f - wy) + s3A[y1l][xi] * wy;
        rB[ry][col] = s3B[y0l][xi] * (1.f - wy) + s3B[y1l][xi] * wy;
    }
    __syncthreads();

    long pbase = ((long)bc * HW + ybase) * (long)HW;
    const float4* gp = (const float4*)(guide + pbase);
    float4* op = (float4*)(out + pbase);

    #pragma unroll 4
    for (int ry = 0; ry < 16; ry++) {
        float4 g = gp[ry * 256 + t];
        float av[4], bv[4];
        #pragma unroll
        for (int u = 0; u < 4; u++) {
            av[u] = rA[ry][x0a[u]] * (1.f - wxa[u]) + rA[ry][x0a[u] + 1] * wxa[u];
            bv[u] = rB[ry][x0a[u]] * (1.f - wxa[u]) + rB[ry][x0a[u] + 1] * wxa[u];
        }
        float4 r;
        r.x = fmaf(av[0], g.x, bv[0]);
        r.y = fmaf(av[1], g.y, bv[1]);
        r.z = fmaf(av[2], g.z, bv[2]);
        r.w = fmaf(av[3], g.w, bv[3]);
        op[ry * 256 + t] = r;
    }
}

// ============================================================
extern "C" void kernel_launch(void* const* d_in, const int* in_sizes, int n_in,
                              void* d_out, int out_size)
{
    const float* guide = (const float*)d_in[0];
    const float* src   = (const float*)d_in[1];
    // d_in[2] = box_w (all ones) — window count is constant 4096, unused
    const float* w1 = (const float*)d_in[3];
    const float* g1 = (const float*)d_in[4];
    const float* b1 = (const float*)d_in[5];
    const float* w2 = (const float*)d_in[6];
    const float* g2 = (const float*)d_in[7];
    const float* b2 = (const float*)d_in[8];
    const float* w3 = (const float*)d_in[9];
    float* out = (float*)d_out;

    k_tilesum<<<TSGRID, 256>>>(guide, src);

    // PDL: dependent launches overlap their ramp with the predecessor.
    cudaLaunchAttribute attr[1];
    attr[0].id = cudaLaunchAttributeProgrammaticStreamSerialization;
    attr[0].val.programmaticStreamSerializationAllowed = 1;

    {
        cudaLaunchConfig_t cfg = {};
        cfg.gridDim = dim3(MBLK, 1, 1);
        cfg.blockDim = dim3(256, 1, 1);
        cfg.dynamicSmemBytes = 0;
        cfg.stream = 0;
        cfg.attrs = attr;
        cfg.numAttrs = 1;
        cudaLaunchKernelEx(&cfg, k_mlp, w1, g1, b1, w2, g2, b2, w3);
    }
    {
        cudaLaunchConfig_t cfg = {};
        cfg.gridDim = dim3(Bn * Cn, 64, 1);
        cfg.blockDim = dim3(256, 1, 1);
        cfg.dynamicSmemBytes = 0;
        cfg.stream = 0;
        cfg.attrs = attr;
        cfg.numAttrs = 1;
        cudaLaunchKernelEx(&cfg, k_apply, guide, out);
    }
}

// round 12
// speedup vs baseline: 1.2055x; 1.1572x over previous
#include <cuda_runtime.h>

#define Bn 4
#define Cn 3
#define HW 1024
#define NT 32            // 32x32 tiles per image dim
#define OP 31            // output positions per dim
#define PP (OP*OP)       // 961
#define NPOS (Bn*PP)     // 3844
#define NPOSP 4096       // padded to 16*256
#define MBLK 16          // mlp blocks (16*256 >= NPOS)
#define TSGRID 768       // tilesum blocks: one wave at 6 CTAs/SM, 4 chunks each
#define INVW (1.0f/4096.0f)
#define INVP (1.0f/3844.0f)
#define EPSV 1e-5f
#define SCL  (30.0f/1023.0f)

// ---- scratch (device globals; no allocation allowed) ----
__device__ unsigned g_c2;      // 16-block barrier counter (self-resets)
__device__ unsigned g_p2;      // 16-block barrier phase (monotonic, replay-safe)
__device__ float g_tile[4][Bn][Cn][NT][NT];   // [stat][b][c][ty][tx]
__device__ float g_part1[MBLK][64];
__device__ float g_part2[MBLK][64];
__device__ float g_A[Cn][NPOSP];
__device__ float g_Bv[Cn][NPOSP];

__device__ __forceinline__ float4 ldcs4(const float* p) {
    return __ldcs((const float4*)p);     // evict-first: read-once data
}

// ============================================================
// Kernel 1: centered 32x32 tile sums, single balanced wave.
// guide loads: default policy (keep in L2 for k_apply re-read).
// src loads: streaming (__ldcs) — read exactly once ever.
// ============================================================
__global__ __launch_bounds__(256, 6) void k_tilesum(
    const float* __restrict__ guide, const float* __restrict__ src)
{
    __shared__ float sh[8][4][4];   // [warp][tile][stat]
    const int t = threadIdx.x;
    const int w = t >> 5, l = t & 31;

    #pragma unroll 1
    for (int i = 0; i < 4; i++) {
        int chunk = blockIdx.x * 4 + i;
        int tx4 = chunk & 7, ty = (chunk >> 3) & 31, bc = chunk >> 8;
        int col = tx4 * 128 + l * 4;
        long base0 = (((long)bc * HW) + (long)(ty * NT + w)) * HW + col;

        float4 G[4], S[4];
        #pragma unroll
        for (int rr = 0; rr < 4; rr++)
            G[rr] = *(const float4*)(guide + base0 + (long)rr * 8 * HW);
        #pragma unroll
        for (int rr = 0; rr < 4; rr++)
            S[rr] = ldcs4(src + base0 + (long)rr * 8 * HW);

        float s1 = 0.f, s2 = 0.f, s3 = 0.f, s4 = 0.f;
        #pragma unroll
        for (int rr = 0; rr < 4; rr++) {
            float x0 = G[rr].x - 0.5f, x1 = G[rr].y - 0.5f,
                  x2 = G[rr].z - 0.5f, x3 = G[rr].w - 0.5f;
            float y0 = S[rr].x - 0.5f, y1 = S[rr].y - 0.5f,
                  y2 = S[rr].z - 0.5f, y3 = S[rr].w - 0.5f;
            s1 += x0 + x1 + x2 + x3;
            s2 += y0 + y1 + y2 + y3;
            s3 = fmaf(x0, y0, fmaf(x1, y1, fmaf(x2, y2, fmaf(x3, y3, s3))));
            s4 = fmaf(x0, x0, fmaf(x1, x1, fmaf(x2, x2, fmaf(x3, x3, s4))));
        }
        #pragma unroll
        for (int o = 4; o; o >>= 1) {
            s1 += __shfl_down_sync(0xffffffffu, s1, o, 8);
            s2 += __shfl_down_sync(0xffffffffu, s2, o, 8);
            s3 += __shfl_down_sync(0xffffffffu, s3, o, 8);
            s4 += __shfl_down_sync(0xffffffffu, s4, o, 8);
        }
        if ((l & 7) == 0) {
            int tt = l >> 3;
            sh[w][tt][0]=s1; sh[w][tt][1]=s2; sh[w][tt][2]=s3; sh[w][tt][3]=s4;
        }
        __syncthreads();
        if (t < 16) {
            int tt = t >> 2, st = t & 3;
            float s = 0.f;
            #pragma unroll
            for (int q = 0; q < 8; q++) s += sh[q][tt][st];
            int b = bc / Cn, c = bc - b * Cn;
            g_tile[st][b][c][ty][tx4 * 4 + tt] = s;
        }
        __syncthreads();
    }
    cudaTriggerProgrammaticLaunchCompletion();
}

// ------------------------------------------------------------
// Sense-reversing barrier among the 16 co-resident mlp blocks.
// Tight volatile spin (16 spinners only; nanosleep wakeup too coarse).
// ------------------------------------------------------------
__device__ __forceinline__ void bar16()
{
    __syncthreads();
    if (threadIdx.x == 0) {
        __threadfence();
        unsigned ph = *(volatile unsigned*)&g_p2;
        if (atomicAdd(&g_c2, 1u) + 1u == MBLK) {
            g_c2 = 0u;
            __threadfence();
            atomicAdd(&g_p2, 1u);
        } else {
            while (*(volatile unsigned*)&g_p2 == ph) { }
        }
        __threadfence();
    }
    __syncthreads();
}

// ============================================================
// Kernel 2: fused MLP. PDL-dependent on k_tilesum.
// ============================================================
__global__ void k_mlp(
    const float* __restrict__ w1, const float* __restrict__ gg1,
    const float* __restrict__ bb1, const float* __restrict__ w2,
    const float* __restrict__ gg2, const float* __restrict__ bb2,
    const float* __restrict__ w3)
{
    __shared__ float sw1[192], sw2[1024], sw3[96], sbn[128];
    __shared__ float sred[8][64], ssum[64], ssc[32], ssf[32];

    const int t = threadIdx.x;
    const int w = t >> 5, l = t & 31;
    const int blk = blockIdx.x;
    const int pos = blk * 256 + t;
    const bool act = pos < NPOS;

    // stage weights while predecessor may still be running
    for (int idx = t; idx < 192; idx += 256) sw1[idx] = w1[idx];
    for (int idx = t; idx < 1024; idx += 256) sw2[idx] = w2[idx];
    if (t < 96) sw3[t] = w3[t];
    if (t < 32) { sbn[t]=gg1[t]; sbn[32+t]=bb1[t]; sbn[64+t]=gg2[t]; sbn[96+t]=bb2[t]; }

    cudaGridDependencySynchronize();    // wait for g_tile
    __syncthreads();

    // ---- window stats ----
    int cpos = act ? pos : 0;
    int b = cpos / PP; int p = cpos - b * PP; int i = p / OP; int j = p - i * OP;

    float h[6], mx[3], my[3];
    #pragma unroll
    for (int c = 0; c < Cn; c++) {
        float S1 = g_tile[0][b][c][i][j] + g_tile[0][b][c][i][j+1]
                 + g_tile[0][b][c][i+1][j] + g_tile[0][b][c][i+1][j+1];
        float S2 = g_tile[1][b][c][i][j] + g_tile[1][b][c][i][j+1]
                 + g_tile[1][b][c][i+1][j] + g_tile[1][b][c][i+1][j+1];
        float S3 = g_tile[2][b][c][i][j] + g_tile[2][b][c][i][j+1]
                 + g_tile[2][b][c][i+1][j] + g_tile[2][b][c][i+1][j+1];
        float S4 = g_tile[3][b][c][i][j] + g_tile[3][b][c][i][j+1]
                 + g_tile[3][b][c][i+1][j] + g_tile[3][b][c][i+1][j+1];
        float ex = S1 * INVW, ey = S2 * INVW;
        mx[c] = ex + 0.5f;
        my[c] = ey + 0.5f;
        h[c]     = S3 * INVW - ex * ey;   // cov_xy (centered)
        h[3 + c] = S4 * INVW - ex * ex;   // var_x
    }

    // ---- layer 1 (6->32) + BN1 partials ----
    float z1[32];
    #pragma unroll
    for (int k = 0; k < 32; k++) {
        float z = 0.f;
        #pragma unroll
        for (int cc = 0; cc < 6; cc++) z = fmaf(sw1[k*6 + cc], h[cc], z);
        z1[k] = z;
        float v  = act ? z : 0.f;
        float v2 = v * v;
        #pragma unroll
        for (int o = 16; o; o >>= 1) {
            v  += __shfl_down_sync(0xffffffffu, v,  o);
            v2 += __shfl_down_sync(0xffffffffu, v2, o);
        }
        if (l == 0) { sred[w][k] = v; sred[w][32 + k] = v2; }
    }
    __syncthreads();
    if (t < 64) {
        float s = 0.f;
        #pragma unroll
        for (int q = 0; q < 8; q++) s += sred[q][t];
        g_part1[blk][t] = s;
    }

    bar16();      // BN1 reduction point

    if (t < 64) {
        float s = 0.f;
        #pragma unroll
        for (int ib = 0; ib < MBLK; ib++) s += g_part1[ib][t];
        ssum[t] = s;
    }
    __syncthreads();
    if (t < 32) {
        float m   = ssum[t] * INVP;
        float var = ssum[32 + t] * INVP - m * m;
        float sc  = sbn[t] * rsqrtf(var + EPSV);
        ssc[t] = sc; ssf[t] = sbn[32 + t] - m * sc;
    }
    __syncthreads();
    #pragma unroll
    for (int k = 0; k < 32; k++)
        z1[k] = fmaxf(fmaf(z1[k], ssc[k], ssf[k]), 0.f);   // a1
    __syncthreads();

    // ---- layer 2 (32->32) + BN2 partials ----
    float z2[32];
    #pragma unroll
    for (int k = 0; k < 32; k++) {
        float z = 0.f;
        #pragma unroll
        for (int cc = 0; cc < 32; cc++) z = fmaf(sw2[k*32 + cc], z1[cc], z);
        z2[k] = z;
        float v  = act ? z : 0.f;
        float v2 = v * v;
        #pragma unroll
        for (int o = 16; o; o >>= 1) {
            v  += __shfl_down_sync(0xffffffffu, v,  o);
            v2 += __shfl_down_sync(0xffffffffu, v2, o);
        }
        if (l == 0) { sred[w][k] = v; sred[w][32 + k] = v2; }
    }
    __syncthreads();
    if (t < 64) {
        float s = 0.f;
        #pragma unroll
        for (int q = 0; q < 8; q++) s += sred[q][t];
        g_part2[blk][t] = s;
    }

    bar16();      // BN2 reduction point

    if (t < 64) {
        float s = 0.f;
        #pragma unroll
        for (int ib = 0; ib < MBLK; ib++) s += g_part2[ib][t];
        ssum[t] = s;
    }
    __syncthreads();
    if (t < 32) {
        float m   = ssum[t] * INVP;
        float var = ssum[32 + t] * INVP - m * m;
        float sc  = sbn[64 + t] * rsqrtf(var + EPSV);
        ssc[t] = sc; ssf[t] = sbn[96 + t] - m * sc;
    }
    __syncthreads();
    #pragma unroll
    for (int k = 0; k < 32; k++)
        z2[k] = fmaxf(fmaf(z2[k], ssc[k], ssf[k]), 0.f);   // a2

    // ---- layer 3 (32->3) => A, b ----
    #pragma unroll
    for (int c = 0; c < Cn; c++) {
        float A = 0.f;
        #pragma unroll
        for (int k = 0; k < 32; k++) A = fmaf(sw3[c*32 + k], z2[k], A);
        g_A[c][pos]  = A;
        g_Bv[c][pos] = my[c] - A * mx[c];
    }
    cudaTriggerProgrammaticLaunchCompletion();
}

// ============================================================
// Kernel 3: bilinear upsample + apply. PDL-dependent on k_mlp.
// out stores use streaming policy so writes don't evict guide.
// ============================================================
__global__ __launch_bounds__(256) void k_apply(
    const float* __restrict__ guide, float* __restrict__ out)
{
    __shared__ float s3A[3][OP], s3B[3][OP];
    __shared__ float rA[16][32], rB[16][32];
    int t = threadIdx.x;
    int bc = blockIdx.x;
    int b = bc / Cn, c = bc - b * Cn;
    int ybase = blockIdx.y * 16;
    int row0 = (int)((float)ybase * SCL);   // first coarse row needed

    int x0a[4]; float wxa[4];
    #pragma unroll
    for (int u = 0; u < 4; u++) {
        float fx = (float)(t * 4 + u) * SCL;
        x0a[u] = (int)fx;
        wxa[u] = fx - (float)x0a[u];
    }

    cudaGridDependencySynchronize();    // wait for g_A / g_Bv

    if (t < 93) {
        int k = t / OP, j = t - k * OP;
        int rsrc = min(row0 + k, OP - 1);
        s3A[k][j] = g_A[c][b * PP + rsrc * OP + j];
        s3B[k][j] = g_Bv[c][b * PP + rsrc * OP + j];
    }
    __syncthreads();

    for (int e = t; e < 512; e += 256) {
        int ry = e >> 5, col = e & 31;
        float fy = (float)(ybase + ry) * SCL;
        int y0 = (int)fy;
        float wy = fy - (float)y0;
        int y0l = y0 - row0;
        int y1l = min(y0 + 1, OP - 1) - row0;
        int xi = min(col, OP - 1);          // col 31 duplicates col 30 (clamp)
        rA[ry][col] = s3A[y0l][xi] * (1.f - wy) + s3A[y1l][xi] * wy;
        rB[ry][col] = s3B[y0l][xi] * (1.f - wy) + s3B[y1l][xi] * wy;
    }
    __syncthreads();

    long pbase = ((long)bc * HW + ybase) * (long)HW;
    const float4* gp = (const float4*)(guide + pbase);
    float4* op = (float4*)(out + pbase);

    #pragma unroll 4
    for (int ry = 0; ry < 16; ry++) {
        float4 g = gp[ry * 256 + t];
        float av[4], bv[4];
        #pragma unroll
        for (int u = 0; u < 4; u++) {
            av[u] = rA[ry][x0a[u]] * (1.f - wxa[u]) + rA[ry][x0a[u] + 1] * wxa[u];
            bv[u] = rB[ry][x0a[u]] * (1.f - wxa[u]) + rB[ry][x0a[u] + 1] * wxa[u];
        }
        float4 r;
        r.x = fmaf(av[0], g.x, bv[0]);
        r.y = fmaf(av[1], g.y, bv[1]);
        r.z = fmaf(av[2], g.z, bv[2]);
        r.w = fmaf(av[3], g.w, bv[3]);
        __stcs(op + ry * 256 + t, r);    // streaming store
    }
}

// ============================================================
extern "C" void kernel_launch(void* const* d_in, const int* in_sizes, int n_in,
                              void* d_out, int out_size)
{
    const float* guide = (const float*)d_in[0];
    const float* src   = (const float*)d_in[1];
    // d_in[2] = box_w (all ones) — window count is constant 4096, unused
    const float* w1 = (const float*)d_in[3];
    const float* g1 = (const float*)d_in[4];
    const float* b1 = (const float*)d_in[5];
    const float* w2 = (const float*)d_in[6];
    const float* g2 = (const float*)d_in[7];
    const float* b2 = (const float*)d_in[8];
    const float* w3 = (const float*)d_in[9];
    float* out = (float*)d_out;

    k_tilesum<<<TSGRID, 256>>>(guide, src);

    // PDL: dependent launches overlap their ramp with the predecessor.
    cudaLaunchAttribute attr[1];
    attr[0].id = cudaLaunchAttributeProgrammaticStreamSerialization;
    attr[0].val.programmaticStreamSerializationAllowed = 1;

    {
        cudaLaunchConfig_t cfg = {};
        cfg.gridDim = dim3(MBLK, 1, 1);
        cfg.blockDim = dim3(256, 1, 1);
        cfg.dynamicSmemBytes = 0;
        cfg.stream = 0;
        cfg.attrs = attr;
        cfg.numAttrs = 1;
        cudaLaunchKernelEx(&cfg, k_mlp, w1, g1, b1, w2, g2, b2, w3);
    }
    {
        cudaLaunchConfig_t cfg = {};
        cfg.gridDim = dim3(Bn * Cn, 64, 1);
        cfg.blockDim = dim3(256, 1, 1);
        cfg.dynamicSmemBytes = 0;
        cfg.stream = 0;
        cfg.attrs = attr;
        cfg.numAttrs = 1;
        cudaLaunchKernelEx(&cfg, k_apply, guide, out);
    }
}